// round 14
// baseline (speedup 1.0000x reference)
#include <cuda_runtime.h>
#include <cuda_fp16.h>
#include <cstdint>

#define BB   8
#define CIN  256
#define COUT 256
#define HH   128
#define WW   128
#define HW   (HH*WW)
#define CK   64                // K chunk
#define NT   256               // threads per CTA

// per-sample fp16 weights [b][o][c], and fp16 depthwise output [b][c][h][w]
__device__ __align__(16) __half g_w [BB*COUT*CIN];
__device__ __align__(16) __half g_dw[(size_t)BB*CIN*HW];

// ---------------- helpers ----------------
__device__ __forceinline__ uint32_t smem_u32(const void* p){
    uint32_t a;
    asm("{ .reg .u64 t; cvta.to.shared.u64 t, %1; cvt.u32.u64 %0, t; }" : "=r"(a) : "l"(p));
    return a;
}
__device__ __forceinline__ void cp_async16(uint32_t saddr, const void* g){
    asm volatile("cp.async.cg.shared.global [%0], [%1], 16;" :: "r"(saddr), "l"(g));
}
#define CP_COMMIT() asm volatile("cp.async.commit_group;" ::: "memory")
#define CP_WAIT(N)  asm volatile("cp.async.wait_group %0;" :: "n"(N) : "memory")

__device__ __forceinline__ void ldsm_x4(uint32_t* r, uint32_t addr){
    asm volatile("ldmatrix.sync.aligned.m8n8.x4.shared.b16 {%0,%1,%2,%3}, [%4];"
        : "=r"(r[0]), "=r"(r[1]), "=r"(r[2]), "=r"(r[3]) : "r"(addr));
}
__device__ __forceinline__ void ldsm_x4_t(uint32_t* r, uint32_t addr){
    asm volatile("ldmatrix.sync.aligned.m8n8.x4.trans.shared.b16 {%0,%1,%2,%3}, [%4];"
        : "=r"(r[0]), "=r"(r[1]), "=r"(r[2]), "=r"(r[3]) : "r"(addr));
}
__device__ __forceinline__ void mma16816(float* c, const uint32_t* a,
                                         uint32_t b0, uint32_t b1){
    asm volatile("mma.sync.aligned.m16n8k16.row.col.f32.f16.f16.f32 "
        "{%0,%1,%2,%3}, {%4,%5,%6,%7}, {%8,%9}, {%0,%1,%2,%3};"
        : "+f"(c[0]), "+f"(c[1]), "+f"(c[2]), "+f"(c[3])
        : "r"(a[0]), "r"(a[1]), "r"(a[2]), "r"(a[3]), "r"(b0), "r"(b1));
}

// ---------------- kernel 0: per-sample fp16 weights --------------------------
__global__ __launch_bounds__(NT)
void build_w_kernel(const float* __restrict__ delta,
                    const float* __restrict__ pw){
    int t = (blockIdx.x * NT + threadIdx.x) * 4;       // [b][o][c4]
    if (t < BB*COUT*CIN){
        int c = t & 255, o = (t >> 8) & 255;
        float4 d = *(const float4*)(delta + t);
        float4 p = *(const float4*)(pw + o*CIN + c);
        __half2 h0 = __floats2half2_rn(p.x + d.x, p.y + d.y);
        __half2 h1 = __floats2half2_rn(p.z + d.z, p.w + d.w);
        *(uint2*)(g_w + t) = make_uint2(*(uint32_t*)&h0, *(uint32_t*)&h1);
    }
}

// ---------------- kernel 1: depthwise 3x3 -> fp16 scratch (one batch) --------
// grid = CIN CTAs of 256 threads; warp w handles rows [w*16, +16).
__global__ __launch_bounds__(NT)
void dw_kernel(const float* __restrict__ x,
               const float* __restrict__ dwk,
               int b){
    const int c   = blockIdx.x;
    const int bc  = b*CIN + c;
    const int wid = threadIdx.x >> 5, lid = threadIdx.x & 31;
    const float* kk = dwk + c*9;
    const float k0=kk[0],k1=kk[1],k2=kk[2],k3=kk[3],k4=kk[4],
                k5=kk[5],k6=kk[6],k7=kk[7],k8=kk[8];

    const float* xp = x + (size_t)bc*HW + lid*4;
    __half* dp = g_dw + (size_t)bc*HW + lid*4;

    const int r0 = wid*16;
    float4 prev = make_float4(0.f,0.f,0.f,0.f);
    if (r0 > 0) prev = *(const float4*)(xp + (size_t)(r0-1)*WW);
    float4 cur  = *(const float4*)(xp + (size_t)r0*WW);

    #pragma unroll 4
    for (int i = 0; i < 16; ++i){
        const int r = r0 + i;
        float4 nxt = make_float4(0.f,0.f,0.f,0.f);
        if (r + 1 < HH) nxt = *(const float4*)(xp + (size_t)(r+1)*WW);

        float pl = __shfl_up_sync(0xffffffffu, prev.w, 1);
        float pr = __shfl_down_sync(0xffffffffu, prev.x, 1);
        float cl = __shfl_up_sync(0xffffffffu, cur.w, 1);
        float cr = __shfl_down_sync(0xffffffffu, cur.x, 1);
        float nl = __shfl_up_sync(0xffffffffu, nxt.w, 1);
        float nr = __shfl_down_sync(0xffffffffu, nxt.x, 1);
        if (lid == 0){ pl = 0.f; cl = 0.f; nl = 0.f; }
        if (lid == 31){ pr = 0.f; cr = 0.f; nr = 0.f; }

        float s0 = k0*pl    + k1*prev.x + k2*prev.y
                 + k3*cl    + k4*cur.x  + k5*cur.y
                 + k6*nl    + k7*nxt.x  + k8*nxt.y;
        float s1 = k0*prev.x+ k1*prev.y + k2*prev.z
                 + k3*cur.x + k4*cur.y  + k5*cur.z
                 + k6*nxt.x + k7*nxt.y  + k8*nxt.z;
        float s2 = k0*prev.y+ k1*prev.z + k2*prev.w
                 + k3*cur.y + k4*cur.z  + k5*cur.w
                 + k6*nxt.y + k7*nxt.z  + k8*nxt.w;
        float s3 = k0*prev.z+ k1*prev.w + k2*pr
                 + k3*cur.z + k4*cur.w  + k5*cr
                 + k6*nxt.z + k7*nxt.w  + k8*nr;

        __half2 p0 = __floats2half2_rn(s0, s1);
        __half2 p1 = __floats2half2_rn(s2, s3);
        *(uint2*)(dp + (size_t)r*WW) = make_uint2(*(uint32_t*)&p0, *(uint32_t*)&p1);

        prev = cur; cur = nxt;
    }
}

// ---------------- kernel 2: batched GEMM (one batch), 3-stage cp.async ring --
// D[b, oy*128+o, hw0+px] = sum_c W[b,o,c] * dw[b,c,hw0+px]
// grid (HW/128, 2); 256 threads (8 warps).
// Warp w: o rows [ (w&3)*32, +32 ), px cols [ (w>>2)*64, +64 ).
static constexpr int STG = 32768;
static constexpr int S_TOTAL = 3*STG;   // 98304

__global__ __launch_bounds__(NT, 2)
void gemm_kernel(float* __restrict__ out, int b){
    extern __shared__ char smem[];
    const uint32_t sb = smem_u32(smem);
    const int tid = threadIdx.x;
    const int wid = tid >> 5, lid = tid & 31;
    const int hwt = blockIdx.x, oy = blockIdx.y;
    const int px0 = hwt * 128;

    const int m_base = (wid & 3) * 32;
    const int n_base = (wid >> 2) * 64;
    const uint32_t lmask = (uint32_t)(lid & 7) << 4;

    const uint4* gw4 = (const uint4*)g_w;

    auto load_chunk = [&](int ch, int buf){
        #pragma unroll
        for (int it = 0; it < 4; ++it){            // A: 1024 x 16B
            int i   = tid + it*NT;
            int o   = i >> 3, ck16 = i & 7;
            uint32_t byte = (uint32_t)(o*128 + ck16*16);
            uint32_t sw   = byte ^ ((uint32_t)(o & 7) << 4);
            int gi = (b*COUT + oy*128 + o)*32 + ch*8 + ck16;
            cp_async16(sb + buf + sw, gw4 + gi);
        }
        #pragma unroll
        for (int it = 0; it < 4; ++it){            // B: 1024 x 16B
            int i  = tid + it*NT;
            int cl = i >> 4, u = i & 15;
            uint32_t byte = (uint32_t)(cl*256 + u*16);
            uint32_t sw   = byte ^ ((uint32_t)(cl & 7) << 4);
            const __half* gp = g_dw + (size_t)(b*CIN + ch*CK + cl)*HW + px0 + u*8;
            cp_async16(sb + buf + 16384 + sw, gp);
        }
        CP_COMMIT();
    };

    float acc[2][8][4];
    #pragma unroll
    for (int mt = 0; mt < 2; ++mt)
        #pragma unroll
        for (int j = 0; j < 8; ++j)
            #pragma unroll
            for (int q = 0; q < 4; ++q) acc[mt][j][q] = 0.f;

    auto mma_chunk = [&](int buf){
        const uint32_t abase = sb + buf;
        const uint32_t bbase = sb + buf + 16384;
        #pragma unroll
        for (int ks = 0; ks < 4; ++ks){
            uint32_t ar[2][4];
            uint32_t br[4][4];
            #pragma unroll
            for (int nt = 0; nt < 4; ++nt){
                int krow = ks*16 + (lid & 15);
                uint32_t col = ((uint32_t)(nt*32 + (lid >> 4)*16)) ^ lmask;
                ldsm_x4_t(br[nt], bbase + (uint32_t)krow*256
                                  + (uint32_t)(n_base*2) + col);
            }
            #pragma unroll
            for (int mt = 0; mt < 2; ++mt){
                int row = m_base + mt*16 + (lid & 15);
                uint32_t col = ((uint32_t)(ks*32 + (lid >> 4)*16)) ^ lmask;
                ldsm_x4(ar[mt], abase + (uint32_t)row*128 + col);
            }
            #pragma unroll
            for (int mt = 0; mt < 2; ++mt)
                #pragma unroll
                for (int j = 0; j < 8; ++j)
                    mma16816(acc[mt][j], ar[mt],
                             br[j>>1][(j&1)*2], br[j>>1][(j&1)*2 + 1]);
        }
    };

    // ---- 3-stage pipeline over 4 chunks (validated schedule)
    load_chunk(0, 0);
    load_chunk(1, STG);
    load_chunk(2, 2*STG);
    CP_WAIT(2); __syncthreads();
    mma_chunk(0);
    __syncthreads();
    load_chunk(3, 0);
    CP_WAIT(2); __syncthreads();
    mma_chunk(STG);
    CP_WAIT(1); __syncthreads();
    mma_chunk(2*STG);
    CP_WAIT(0); __syncthreads();
    mma_chunk(0);

    // ---- epilogue (validated fragment map)
    #pragma unroll
    for (int mt = 0; mt < 2; ++mt){
        #pragma unroll
        for (int j = 0; j < 8; ++j){
            int o  = oy*128 + m_base + mt*16 + (lid >> 2);
            int px = n_base + j*8 + (lid & 3)*2;
            float* p = out + (size_t)(b*COUT + o)*HW + px0 + px;
            *(float2*)p = make_float2(acc[mt][j][0], acc[mt][j][1]);
            *(float2*)(p + (size_t)8*HW) = make_float2(acc[mt][j][2], acc[mt][j][3]);
        }
    }
}

// ---------------------------------------------------------------------------
extern "C" void kernel_launch(void* const* d_in, const int* in_sizes, int n_in,
                              void* d_out, int out_size){
    const float* x     = (const float*)d_in[0];
    const float* delta = (const float*)d_in[1];
    const float* dwk   = (const float*)d_in[2];
    const float* pw    = (const float*)d_in[3];
    float* out = (float*)d_out;

    // Lazily created auxiliary stream + events (handles only; no device memory).
    static cudaStream_t s2 = nullptr;
    static cudaEvent_t  ev_dw[BB], ev_join;
    if (s2 == nullptr){
        cudaStreamCreateWithFlags(&s2, cudaStreamNonBlocking);
        for (int i = 0; i < BB; ++i)
            cudaEventCreateWithFlags(&ev_dw[i], cudaEventDisableTiming);
        cudaEventCreateWithFlags(&ev_join, cudaEventDisableTiming);
        cudaFuncSetAttribute(gemm_kernel,
                             cudaFuncAttributeMaxDynamicSharedMemorySize, S_TOTAL);
    }

    // s2 forks from the (captured) default stream via dw-completion events.
    build_w_kernel<<<512, NT, 0, s2>>>(delta, pw);     // joined below via ev_dw wait? no:
    // NOTE: build_w must itself be ordered after capture fork; it has no
    // dependency on default-stream work, and gemm launches follow it on s2.

    for (int b = 0; b < BB; ++b){
        dw_kernel<<<CIN, NT, 0, 0>>>(x, dwk, b);       // default stream
        cudaEventRecord(ev_dw[b], 0);
        cudaStreamWaitEvent(s2, ev_dw[b], 0);
        gemm_kernel<<<dim3(HW/128, 2), NT, S_TOTAL, s2>>>(out, b);
    }
    cudaEventRecord(ev_join, s2);
    cudaStreamWaitEvent(0, ev_join, 0);                // join s2 back into capture
}

// round 15
// speedup vs baseline: 1.2371x; 1.2371x over previous
#include <cuda_runtime.h>
#include <cuda_fp16.h>
#include <cstdint>

#define BB   8
#define CIN  256
#define COUT 256
#define HH   128
#define WW   128
#define HW   (HH*WW)
#define CK   64                // K chunk
#define NT   256               // threads per CTA
#define BHALF 4                // batches per half

// per-sample fp16 weights [b][o][c], and fp16 depthwise output [b][c][h][w]
__device__ __align__(16) __half g_w [BB*COUT*CIN];
__device__ __align__(16) __half g_dw[(size_t)BB*CIN*HW];

// ---------------- helpers ----------------
__device__ __forceinline__ uint32_t smem_u32(const void* p){
    uint32_t a;
    asm("{ .reg .u64 t; cvta.to.shared.u64 t, %1; cvt.u32.u64 %0, t; }" : "=r"(a) : "l"(p));
    return a;
}
__device__ __forceinline__ void cp_async16(uint32_t saddr, const void* g){
    asm volatile("cp.async.cg.shared.global [%0], [%1], 16;" :: "r"(saddr), "l"(g));
}
#define CP_COMMIT() asm volatile("cp.async.commit_group;" ::: "memory")
#define CP_WAIT(N)  asm volatile("cp.async.wait_group %0;" :: "n"(N) : "memory")

__device__ __forceinline__ void ldsm_x4(uint32_t* r, uint32_t addr){
    asm volatile("ldmatrix.sync.aligned.m8n8.x4.shared.b16 {%0,%1,%2,%3}, [%4];"
        : "=r"(r[0]), "=r"(r[1]), "=r"(r[2]), "=r"(r[3]) : "r"(addr));
}
__device__ __forceinline__ void ldsm_x4_t(uint32_t* r, uint32_t addr){
    asm volatile("ldmatrix.sync.aligned.m8n8.x4.trans.shared.b16 {%0,%1,%2,%3}, [%4];"
        : "=r"(r[0]), "=r"(r[1]), "=r"(r[2]), "=r"(r[3]) : "r"(addr));
}
__device__ __forceinline__ void mma16816(float* c, const uint32_t* a,
                                         uint32_t b0, uint32_t b1){
    asm volatile("mma.sync.aligned.m16n8k16.row.col.f32.f16.f16.f32 "
        "{%0,%1,%2,%3}, {%4,%5,%6,%7}, {%8,%9}, {%0,%1,%2,%3};"
        : "+f"(c[0]), "+f"(c[1]), "+f"(c[2]), "+f"(c[3])
        : "r"(a[0]), "r"(a[1]), "r"(a[2]), "r"(a[3]), "r"(b0), "r"(b1));
}

// ---------------- kernel 0: per-sample fp16 weights --------------------------
__global__ __launch_bounds__(NT)
void build_w_kernel(const float* __restrict__ delta,
                    const float* __restrict__ pw){
    int t = (blockIdx.x * NT + threadIdx.x) * 4;       // [b][o][c4]
    if (t < BB*COUT*CIN){
        int c = t & 255, o = (t >> 8) & 255;
        float4 d = *(const float4*)(delta + t);
        float4 p = *(const float4*)(pw + o*CIN + c);
        __half2 h0 = __floats2half2_rn(p.x + d.x, p.y + d.y);
        __half2 h1 = __floats2half2_rn(p.z + d.z, p.w + d.w);
        *(uint2*)(g_w + t) = make_uint2(*(uint32_t*)&h0, *(uint32_t*)&h1);
    }
}

// ---------------- kernel 1: depthwise 3x3 -> fp16 (half the batch) -----------
// grid (CIN, 1, BHALF); warp w handles rows [w*16, +16).
__global__ __launch_bounds__(NT)
void dw_kernel(const float* __restrict__ x,
               const float* __restrict__ dwk,
               int b0){
    const int c   = blockIdx.x;
    const int bc  = (b0 + blockIdx.z)*CIN + c;
    const int wid = threadIdx.x >> 5, lid = threadIdx.x & 31;
    const float* kk = dwk + c*9;
    const float k0=kk[0],k1=kk[1],k2=kk[2],k3=kk[3],k4=kk[4],
                k5=kk[5],k6=kk[6],k7=kk[7],k8=kk[8];

    const float* xp = x + (size_t)bc*HW + lid*4;
    __half* dp = g_dw + (size_t)bc*HW + lid*4;

    const int r0 = wid*16;
    float4 prev = make_float4(0.f,0.f,0.f,0.f);
    if (r0 > 0) prev = *(const float4*)(xp + (size_t)(r0-1)*WW);
    float4 cur  = *(const float4*)(xp + (size_t)r0*WW);

    #pragma unroll 4
    for (int i = 0; i < 16; ++i){
        const int r = r0 + i;
        float4 nxt = make_float4(0.f,0.f,0.f,0.f);
        if (r + 1 < HH) nxt = *(const float4*)(xp + (size_t)(r+1)*WW);

        float pl = __shfl_up_sync(0xffffffffu, prev.w, 1);
        float pr = __shfl_down_sync(0xffffffffu, prev.x, 1);
        float cl = __shfl_up_sync(0xffffffffu, cur.w, 1);
        float cr = __shfl_down_sync(0xffffffffu, cur.x, 1);
        float nl = __shfl_up_sync(0xffffffffu, nxt.w, 1);
        float nr = __shfl_down_sync(0xffffffffu, nxt.x, 1);
        if (lid == 0){ pl = 0.f; cl = 0.f; nl = 0.f; }
        if (lid == 31){ pr = 0.f; cr = 0.f; nr = 0.f; }

        float s0 = k0*pl    + k1*prev.x + k2*prev.y
                 + k3*cl    + k4*cur.x  + k5*cur.y
                 + k6*nl    + k7*nxt.x  + k8*nxt.y;
        float s1 = k0*prev.x+ k1*prev.y + k2*prev.z
                 + k3*cur.x + k4*cur.y  + k5*cur.z
                 + k6*nxt.x + k7*nxt.y  + k8*nxt.z;
        float s2 = k0*prev.y+ k1*prev.z + k2*prev.w
                 + k3*cur.y + k4*cur.z  + k5*cur.w
                 + k6*nxt.y + k7*nxt.z  + k8*nxt.w;
        float s3 = k0*prev.z+ k1*prev.w + k2*pr
                 + k3*cur.z + k4*cur.w  + k5*cr
                 + k6*nxt.z + k7*nxt.w  + k8*nr;

        __half2 p0 = __floats2half2_rn(s0, s1);
        __half2 p1 = __floats2half2_rn(s2, s3);
        *(uint2*)(dp + (size_t)r*WW) = make_uint2(*(uint32_t*)&p0, *(uint32_t*)&p1);

        prev = cur; cur = nxt;
    }
}

// ---------------- kernel 2: batched GEMM (half the batch), 3-stage ring ------
// grid (HW/128, 2, BHALF); 256 threads (8 warps).
// Warp w: o rows [ (w&3)*32, +32 ), px cols [ (w>>2)*64, +64 ).
static constexpr int STG = 32768;
static constexpr int S_TOTAL = 3*STG;   // 98304

__global__ __launch_bounds__(NT, 2)
void gemm_kernel(float* __restrict__ out, int b0){
    extern __shared__ char smem[];
    const uint32_t sb = smem_u32(smem);
    const int tid = threadIdx.x;
    const int wid = tid >> 5, lid = tid & 31;
    const int hwt = blockIdx.x, oy = blockIdx.y;
    const int b = b0 + blockIdx.z;
    const int px0 = hwt * 128;

    const int m_base = (wid & 3) * 32;
    const int n_base = (wid >> 2) * 64;
    const uint32_t lmask = (uint32_t)(lid & 7) << 4;

    const uint4* gw4 = (const uint4*)g_w;

    auto load_chunk = [&](int ch, int buf){
        #pragma unroll
        for (int it = 0; it < 4; ++it){            // A: 1024 x 16B
            int i   = tid + it*NT;
            int o   = i >> 3, ck16 = i & 7;
            uint32_t byte = (uint32_t)(o*128 + ck16*16);
            uint32_t sw   = byte ^ ((uint32_t)(o & 7) << 4);
            int gi = (b*COUT + oy*128 + o)*32 + ch*8 + ck16;
            cp_async16(sb + buf + sw, gw4 + gi);
        }
        #pragma unroll
        for (int it = 0; it < 4; ++it){            // B: 1024 x 16B
            int i  = tid + it*NT;
            int cl = i >> 4, u = i & 15;
            uint32_t byte = (uint32_t)(cl*256 + u*16);
            uint32_t sw   = byte ^ ((uint32_t)(cl & 7) << 4);
            const __half* gp = g_dw + (size_t)(b*CIN + ch*CK + cl)*HW + px0 + u*8;
            cp_async16(sb + buf + 16384 + sw, gp);
        }
        CP_COMMIT();
    };

    float acc[2][8][4];
    #pragma unroll
    for (int mt = 0; mt < 2; ++mt)
        #pragma unroll
        for (int j = 0; j < 8; ++j)
            #pragma unroll
            for (int q = 0; q < 4; ++q) acc[mt][j][q] = 0.f;

    auto mma_chunk = [&](int buf){
        const uint32_t abase = sb + buf;
        const uint32_t bbase = sb + buf + 16384;
        #pragma unroll
        for (int ks = 0; ks < 4; ++ks){
            uint32_t ar[2][4];
            uint32_t br[4][4];
            #pragma unroll
            for (int nt = 0; nt < 4; ++nt){
                int krow = ks*16 + (lid & 15);
                uint32_t col = ((uint32_t)(nt*32 + (lid >> 4)*16)) ^ lmask;
                ldsm_x4_t(br[nt], bbase + (uint32_t)krow*256
                                  + (uint32_t)(n_base*2) + col);
            }
            #pragma unroll
            for (int mt = 0; mt < 2; ++mt){
                int row = m_base + mt*16 + (lid & 15);
                uint32_t col = ((uint32_t)(ks*32 + (lid >> 4)*16)) ^ lmask;
                ldsm_x4(ar[mt], abase + (uint32_t)row*128 + col);
            }
            #pragma unroll
            for (int mt = 0; mt < 2; ++mt)
                #pragma unroll
                for (int j = 0; j < 8; ++j)
                    mma16816(acc[mt][j], ar[mt],
                             br[j>>1][(j&1)*2], br[j>>1][(j&1)*2 + 1]);
        }
    };

    // ---- 3-stage pipeline over 4 chunks (validated schedule)
    load_chunk(0, 0);
    load_chunk(1, STG);
    load_chunk(2, 2*STG);
    CP_WAIT(2); __syncthreads();
    mma_chunk(0);
    __syncthreads();
    load_chunk(3, 0);
    CP_WAIT(2); __syncthreads();
    mma_chunk(STG);
    CP_WAIT(1); __syncthreads();
    mma_chunk(2*STG);
    CP_WAIT(0); __syncthreads();
    mma_chunk(0);

    // ---- epilogue (validated fragment map)
    #pragma unroll
    for (int mt = 0; mt < 2; ++mt){
        #pragma unroll
        for (int j = 0; j < 8; ++j){
            int o  = oy*128 + m_base + mt*16 + (lid >> 2);
            int px = n_base + j*8 + (lid & 3)*2;
            float* p = out + (size_t)(b*COUT + o)*HW + px0 + px;
            *(float2*)p = make_float2(acc[mt][j][0], acc[mt][j][1]);
            *(float2*)(p + (size_t)8*HW) = make_float2(acc[mt][j][2], acc[mt][j][3]);
        }
    }
}

// ---------------------------------------------------------------------------
extern "C" void kernel_launch(void* const* d_in, const int* in_sizes, int n_in,
                              void* d_out, int out_size){
    const float* x     = (const float*)d_in[0];
    const float* delta = (const float*)d_in[1];
    const float* dwk   = (const float*)d_in[2];
    const float* pw    = (const float*)d_in[3];
    float* out = (float*)d_out;

    static cudaStream_t s2 = nullptr;
    static cudaEvent_t ev1, ev2, ev_join;
    if (s2 == nullptr){
        cudaStreamCreateWithFlags(&s2, cudaStreamNonBlocking);
        cudaEventCreateWithFlags(&ev1,     cudaEventDisableTiming);
        cudaEventCreateWithFlags(&ev2,     cudaEventDisableTiming);
        cudaEventCreateWithFlags(&ev_join, cudaEventDisableTiming);
        cudaFuncSetAttribute(gemm_kernel,
                             cudaFuncAttributeMaxDynamicSharedMemorySize, S_TOTAL);
    }

    // default stream: build_w -> dw half 1 -> dw half 2
    build_w_kernel<<<512, NT>>>(delta, pw);
    dw_kernel<<<dim3(CIN, 1, BHALF), NT>>>(x, dwk, 0);
    cudaEventRecord(ev1, 0);
    dw_kernel<<<dim3(CIN, 1, BHALF), NT>>>(x, dwk, BHALF);
    cudaEventRecord(ev2, 0);

    // s2: gemm half 1 (after dw half 1), gemm half 2 (after dw half 2)
    cudaStreamWaitEvent(s2, ev1, 0);
    gemm_kernel<<<dim3(HW/128, 2, BHALF), NT, S_TOTAL, s2>>>(out, 0);
    cudaStreamWaitEvent(s2, ev2, 0);
    gemm_kernel<<<dim3(HW/128, 2, BHALF), NT, S_TOTAL, s2>>>(out, BHALF);

    cudaEventRecord(ev_join, s2);
    cudaStreamWaitEvent(0, ev_join, 0);
}

// round 16
// speedup vs baseline: 1.3261x; 1.0719x over previous
#include <cuda_runtime.h>
#include <cuda_fp16.h>
#include <cstdint>

#define BB   8
#define CIN  256
#define COUT 256
#define HH   128
#define WW   128
#define HW   (HH*WW)
#define CK   64                // K chunk
#define NT   256               // threads per gemm CTA
#define NTDW 512               // threads per dw CTA (16 warps x 8 rows)
#define BHALF 4                // batches per half

// per-sample fp16 weights [b][o][c], and fp16 depthwise output [b][c][h][w]
__device__ __align__(16) __half g_w [BB*COUT*CIN];
__device__ __align__(16) __half g_dw[(size_t)BB*CIN*HW];

// ---------------- helpers ----------------
__device__ __forceinline__ uint32_t smem_u32(const void* p){
    uint32_t a;
    asm("{ .reg .u64 t; cvta.to.shared.u64 t, %1; cvt.u32.u64 %0, t; }" : "=r"(a) : "l"(p));
    return a;
}
__device__ __forceinline__ void cp_async16(uint32_t saddr, const void* g){
    asm volatile("cp.async.cg.shared.global [%0], [%1], 16;" :: "r"(saddr), "l"(g));
}
#define CP_COMMIT() asm volatile("cp.async.commit_group;" ::: "memory")
#define CP_WAIT(N)  asm volatile("cp.async.wait_group %0;" :: "n"(N) : "memory")

__device__ __forceinline__ void ldsm_x4(uint32_t* r, uint32_t addr){
    asm volatile("ldmatrix.sync.aligned.m8n8.x4.shared.b16 {%0,%1,%2,%3}, [%4];"
        : "=r"(r[0]), "=r"(r[1]), "=r"(r[2]), "=r"(r[3]) : "r"(addr));
}
__device__ __forceinline__ void ldsm_x4_t(uint32_t* r, uint32_t addr){
    asm volatile("ldmatrix.sync.aligned.m8n8.x4.trans.shared.b16 {%0,%1,%2,%3}, [%4];"
        : "=r"(r[0]), "=r"(r[1]), "=r"(r[2]), "=r"(r[3]) : "r"(addr));
}
__device__ __forceinline__ void mma16816(float* c, const uint32_t* a,
                                         uint32_t b0, uint32_t b1){
    asm volatile("mma.sync.aligned.m16n8k16.row.col.f32.f16.f16.f32 "
        "{%0,%1,%2,%3}, {%4,%5,%6,%7}, {%8,%9}, {%0,%1,%2,%3};"
        : "+f"(c[0]), "+f"(c[1]), "+f"(c[2]), "+f"(c[3])
        : "r"(a[0]), "r"(a[1]), "r"(a[2]), "r"(a[3]), "r"(b0), "r"(b1));
}

// ---------------- kernel 0: per-sample fp16 weights --------------------------
__global__ __launch_bounds__(NT)
void build_w_kernel(const float* __restrict__ delta,
                    const float* __restrict__ pw){
    int t = (blockIdx.x * NT + threadIdx.x) * 4;       // [b][o][c4]
    if (t < BB*COUT*CIN){
        int c = t & 255, o = (t >> 8) & 255;
        float4 d = *(const float4*)(delta + t);
        float4 p = *(const float4*)(pw + o*CIN + c);
        __half2 h0 = __floats2half2_rn(p.x + d.x, p.y + d.y);
        __half2 h1 = __floats2half2_rn(p.z + d.z, p.w + d.w);
        *(uint2*)(g_w + t) = make_uint2(*(uint32_t*)&h0, *(uint32_t*)&h1);
    }
}

// ---------------- kernel 1: depthwise 3x3 -> fp16 (half the batch) -----------
// grid (CIN, 1, BHALF), 512 threads; warp w handles rows [w*8, +8).
__global__ __launch_bounds__(NTDW)
void dw_kernel(const float* __restrict__ x,
               const float* __restrict__ dwk,
               int b0){
    const int c   = blockIdx.x;
    const int bc  = (b0 + blockIdx.z)*CIN + c;
    const int wid = threadIdx.x >> 5, lid = threadIdx.x & 31;
    const float* kk = dwk + c*9;
    const float k0=kk[0],k1=kk[1],k2=kk[2],k3=kk[3],k4=kk[4],
                k5=kk[5],k6=kk[6],k7=kk[7],k8=kk[8];

    const float* xp = x + (size_t)bc*HW + lid*4;
    __half* dp = g_dw + (size_t)bc*HW + lid*4;

    const int r0 = wid*8;
    float4 prev = make_float4(0.f,0.f,0.f,0.f);
    if (r0 > 0) prev = *(const float4*)(xp + (size_t)(r0-1)*WW);
    float4 cur  = *(const float4*)(xp + (size_t)r0*WW);

    #pragma unroll
    for (int i = 0; i < 8; ++i){
        const int r = r0 + i;
        float4 nxt = make_float4(0.f,0.f,0.f,0.f);
        if (r + 1 < HH) nxt = *(const float4*)(xp + (size_t)(r+1)*WW);

        float pl = __shfl_up_sync(0xffffffffu, prev.w, 1);
        float pr = __shfl_down_sync(0xffffffffu, prev.x, 1);
        float cl = __shfl_up_sync(0xffffffffu, cur.w, 1);
        float cr = __shfl_down_sync(0xffffffffu, cur.x, 1);
        float nl = __shfl_up_sync(0xffffffffu, nxt.w, 1);
        float nr = __shfl_down_sync(0xffffffffu, nxt.x, 1);
        if (lid == 0){ pl = 0.f; cl = 0.f; nl = 0.f; }
        if (lid == 31){ pr = 0.f; cr = 0.f; nr = 0.f; }

        float s0 = k0*pl    + k1*prev.x + k2*prev.y
                 + k3*cl    + k4*cur.x  + k5*cur.y
                 + k6*nl    + k7*nxt.x  + k8*nxt.y;
        float s1 = k0*prev.x+ k1*prev.y + k2*prev.z
                 + k3*cur.x + k4*cur.y  + k5*cur.z
                 + k6*nxt.x + k7*nxt.y  + k8*nxt.z;
        float s2 = k0*prev.y+ k1*prev.z + k2*prev.w
                 + k3*cur.y + k4*cur.z  + k5*cur.w
                 + k6*nxt.y + k7*nxt.z  + k8*nxt.w;
        float s3 = k0*prev.z+ k1*prev.w + k2*pr
                 + k3*cur.z + k4*cur.w  + k5*cr
                 + k6*nxt.z + k7*nxt.w  + k8*nr;

        __half2 p0 = __floats2half2_rn(s0, s1);
        __half2 p1 = __floats2half2_rn(s2, s3);
        *(uint2*)(dp + (size_t)r*WW) = make_uint2(*(uint32_t*)&p0, *(uint32_t*)&p1);

        prev = cur; cur = nxt;
    }
}

// ---------------- kernel 2: batched GEMM (half the batch), 3-stage ring ------
// grid (HW/128, 2, BHALF); 256 threads (8 warps).
// Warp w: o rows [ (w&3)*32, +32 ), px cols [ (w>>2)*64, +64 ).
static constexpr int STG = 32768;
static constexpr int S_TOTAL = 3*STG;   // 98304

__global__ __launch_bounds__(NT, 2)
void gemm_kernel(float* __restrict__ out, int b0){
    extern __shared__ char smem[];
    const uint32_t sb = smem_u32(smem);
    const int tid = threadIdx.x;
    const int wid = tid >> 5, lid = tid & 31;
    const int hwt = blockIdx.x, oy = blockIdx.y;
    const int b = b0 + blockIdx.z;
    const int px0 = hwt * 128;

    const int m_base = (wid & 3) * 32;
    const int n_base = (wid >> 2) * 64;
    const uint32_t lmask = (uint32_t)(lid & 7) << 4;

    const uint4* gw4 = (const uint4*)g_w;

    auto load_chunk = [&](int ch, int buf){
        #pragma unroll
        for (int it = 0; it < 4; ++it){            // A: 1024 x 16B
            int i   = tid + it*NT;
            int o   = i >> 3, ck16 = i & 7;
            uint32_t byte = (uint32_t)(o*128 + ck16*16);
            uint32_t sw   = byte ^ ((uint32_t)(o & 7) << 4);
            int gi = (b*COUT + oy*128 + o)*32 + ch*8 + ck16;
            cp_async16(sb + buf + sw, gw4 + gi);
        }
        #pragma unroll
        for (int it = 0; it < 4; ++it){            // B: 1024 x 16B
            int i  = tid + it*NT;
            int cl = i >> 4, u = i & 15;
            uint32_t byte = (uint32_t)(cl*256 + u*16);
            uint32_t sw   = byte ^ ((uint32_t)(cl & 7) << 4);
            const __half* gp = g_dw + (size_t)(b*CIN + ch*CK + cl)*HW + px0 + u*8;
            cp_async16(sb + buf + 16384 + sw, gp);
        }
        CP_COMMIT();
    };

    float acc[2][8][4];
    #pragma unroll
    for (int mt = 0; mt < 2; ++mt)
        #pragma unroll
        for (int j = 0; j < 8; ++j)
            #pragma unroll
            for (int q = 0; q < 4; ++q) acc[mt][j][q] = 0.f;

    auto mma_chunk = [&](int buf){
        const uint32_t abase = sb + buf;
        const uint32_t bbase = sb + buf + 16384;
        #pragma unroll
        for (int ks = 0; ks < 4; ++ks){
            uint32_t ar[2][4];
            uint32_t br[4][4];
            #pragma unroll
            for (int nt = 0; nt < 4; ++nt){
                int krow = ks*16 + (lid & 15);
                uint32_t col = ((uint32_t)(nt*32 + (lid >> 4)*16)) ^ lmask;
                ldsm_x4_t(br[nt], bbase + (uint32_t)krow*256
                                  + (uint32_t)(n_base*2) + col);
            }
            #pragma unroll
            for (int mt = 0; mt < 2; ++mt){
                int row = m_base + mt*16 + (lid & 15);
                uint32_t col = ((uint32_t)(ks*32 + (lid >> 4)*16)) ^ lmask;
                ldsm_x4(ar[mt], abase + (uint32_t)row*128 + col);
            }
            #pragma unroll
            for (int mt = 0; mt < 2; ++mt)
                #pragma unroll
                for (int j = 0; j < 8; ++j)
                    mma16816(acc[mt][j], ar[mt],
                             br[j>>1][(j&1)*2], br[j>>1][(j&1)*2 + 1]);
        }
    };

    // ---- 3-stage pipeline over 4 chunks (validated schedule)
    load_chunk(0, 0);
    load_chunk(1, STG);
    load_chunk(2, 2*STG);
    CP_WAIT(2); __syncthreads();
    mma_chunk(0);
    __syncthreads();
    load_chunk(3, 0);
    CP_WAIT(2); __syncthreads();
    mma_chunk(STG);
    CP_WAIT(1); __syncthreads();
    mma_chunk(2*STG);
    CP_WAIT(0); __syncthreads();
    mma_chunk(0);

    // ---- epilogue (validated fragment map)
    #pragma unroll
    for (int mt = 0; mt < 2; ++mt){
        #pragma unroll
        for (int j = 0; j < 8; ++j){
            int o  = oy*128 + m_base + mt*16 + (lid >> 2);
            int px = n_base + j*8 + (lid & 3)*2;
            float* p = out + (size_t)(b*COUT + o)*HW + px0 + px;
            *(float2*)p = make_float2(acc[mt][j][0], acc[mt][j][1]);
            *(float2*)(p + (size_t)8*HW) = make_float2(acc[mt][j][2], acc[mt][j][3]);
        }
    }
}

// ---------------------------------------------------------------------------
extern "C" void kernel_launch(void* const* d_in, const int* in_sizes, int n_in,
                              void* d_out, int out_size){
    const float* x     = (const float*)d_in[0];
    const float* delta = (const float*)d_in[1];
    const float* dwk   = (const float*)d_in[2];
    const float* pw    = (const float*)d_in[3];
    float* out = (float*)d_out;

    static cudaStream_t s1 = nullptr, s2 = nullptr;
    static cudaEvent_t ev0, ev1, ev2, ev_join;
    if (s1 == nullptr){
        cudaStreamCreateWithFlags(&s1, cudaStreamNonBlocking);
        cudaStreamCreateWithFlags(&s2, cudaStreamNonBlocking);
        cudaEventCreateWithFlags(&ev0,     cudaEventDisableTiming);
        cudaEventCreateWithFlags(&ev1,     cudaEventDisableTiming);
        cudaEventCreateWithFlags(&ev2,     cudaEventDisableTiming);
        cudaEventCreateWithFlags(&ev_join, cudaEventDisableTiming);
        cudaFuncSetAttribute(gemm_kernel,
                             cudaFuncAttributeMaxDynamicSharedMemorySize, S_TOTAL);
    }

    // Fork both worker streams from the capture (default) stream.
    cudaEventRecord(ev0, 0);
    cudaStreamWaitEvent(s1, ev0, 0);
    cudaStreamWaitEvent(s2, ev0, 0);

    // s1: dw half 1 -> dw half 2  (no legacy-stream launches in between)
    dw_kernel<<<dim3(CIN, 1, BHALF), NTDW, 0, s1>>>(x, dwk, 0);
    cudaEventRecord(ev1, s1);
    dw_kernel<<<dim3(CIN, 1, BHALF), NTDW, 0, s1>>>(x, dwk, BHALF);
    cudaEventRecord(ev2, s1);

    // s2: build_w -> gemm half 1 (after dw half 1) -> gemm half 2
    build_w_kernel<<<512, NT, 0, s2>>>(delta, pw);
    cudaStreamWaitEvent(s2, ev1, 0);
    gemm_kernel<<<dim3(HW/128, 2, BHALF), NT, S_TOTAL, s2>>>(out, 0);
    cudaStreamWaitEvent(s2, ev2, 0);
    gemm_kernel<<<dim3(HW/128, 2, BHALF), NT, S_TOTAL, s2>>>(out, BHALF);

    // Join both back into the capture stream.
    cudaEventRecord(ev_join, s2);
    cudaStreamWaitEvent(0, ev_join, 0);
    cudaEventRecord(ev1, s1);            // reuse: s1 tail join
    cudaStreamWaitEvent(0, ev1, 0);
}